// round 1
// baseline (speedup 1.0000x reference)
#include <cuda_runtime.h>
#include <cuda_bf16.h>

#define N_PTS   32768
#define S_NBR   32
#define C_IN    64
#define C_OUT   128
#define NS      (N_PTS * S_NBR)   // 1048576
#define EPSBN   1e-5f

// Scratch (device globals; no allocation allowed)
__device__ float g_agg[C_IN * N_PTS];     // [c][n]  8 MB
__device__ float g_ypre[C_OUT * N_PTS];   // [o][n] 16 MB
__device__ float g_rpre[C_OUT * N_PTS];   // [o][n] 16 MB
__device__ float g_stats[4 * C_OUT];      // [sum_f | sumsq_f | sum_r | sumsq_r]

// ---------------------------------------------------------------------------
__global__ void k_zero_stats() {
    g_stats[threadIdx.x] = 0.0f;
}

// ---------------------------------------------------------------------------
// Aggregation: one warp per point, lane = neighbour sample s.
// agg[n][c] = sum_s relu(pos[n,s]·W_int[c] + b_int[c]) * NP[3+c, n, s]
// Output transposed to g_agg[c][n] for coalesced downstream reads.
__global__ __launch_bounds__(1024) void k_agg(
    const float* __restrict__ xyz,     // [N][3]
    const float* __restrict__ np,      // [67][N][S]
    const float* __restrict__ Wint,    // [64][3]
    const float* __restrict__ bint)    // [64]
{
    __shared__ float4 wq[C_IN];             // {w0,w1,w2,bias}
    __shared__ float aggs[C_IN][32];        // [c][point-in-block]
    int tid = threadIdx.x;
    if (tid < C_IN)
        wq[tid] = make_float4(Wint[tid*3+0], Wint[tid*3+1], Wint[tid*3+2], bint[tid]);
    __syncthreads();

    int w = tid >> 5;          // point within block
    int s = tid & 31;          // neighbour sample (lane)
    int n = blockIdx.x * 32 + w;

    float x0 = xyz[n*3 + 0];
    float x1 = xyz[n*3 + 1];
    float x2 = xyz[n*3 + 2];

    int base = n * S_NBR + s;
    float p0 = np[0*NS + base] - x0;
    float p1 = np[1*NS + base] - x1;
    float p2 = np[2*NS + base] - x2;

    const float* __restrict__ feat = np + 3*NS + base;

    #pragma unroll 8
    for (int c = 0; c < C_IN; c++) {
        float4 wc = wq[c];
        float h = fmaf(p0, wc.x, fmaf(p1, wc.y, fmaf(p2, wc.z, wc.w)));
        h = fmaxf(h, 0.0f);
        float v = h * feat[c * NS];
        v += __shfl_xor_sync(0xffffffffu, v, 16);
        v += __shfl_xor_sync(0xffffffffu, v, 8);
        v += __shfl_xor_sync(0xffffffffu, v, 4);
        v += __shfl_xor_sync(0xffffffffu, v, 2);
        v += __shfl_xor_sync(0xffffffffu, v, 1);
        if (s == 0) aggs[c][w] = v;
    }
    __syncthreads();

    // coalesced transposed write: g_agg[c][n0 + p]
    int n0 = blockIdx.x * 32;
    #pragma unroll
    for (int i = tid; i < C_IN * 32; i += 1024) {
        int c = i >> 5, p = i & 31;
        g_agg[c * N_PTS + n0 + p] = aggs[c][p];
    }
}

// ---------------------------------------------------------------------------
// GEMV 64 -> 128 per point + BN statistics (sum, sumsq per output channel).
// in: [64][N] channel-major.  SEL=0: feature path (g_agg -> g_ypre, stats 0/128)
//                             SEL=1: residual path (features -> g_rpre, stats 256/384)
template<int SEL>
__global__ __launch_bounds__(256) void k_gemv_stats(
    const float* __restrict__ in_ext,  // used when SEL==1; SEL==0 reads g_agg
    const float* __restrict__ W,       // [128][64]
    const float* __restrict__ b)       // [128]
{
    __shared__ float4 Ws[C_OUT * (C_IN/4)];  // 32 KB
    __shared__ float  bs[C_OUT];
    __shared__ float  ssum[C_OUT], ssq[C_OUT];

    int tid = threadIdx.x;
    const float4* W4 = (const float4*)W;
    for (int i = tid; i < C_OUT * (C_IN/4); i += 256) Ws[i] = W4[i];
    for (int i = tid; i < C_OUT; i += 256) { bs[i] = b[i]; ssum[i] = 0.0f; ssq[i] = 0.0f; }
    __syncthreads();

    int n = blockIdx.x * 256 + tid;
    int lane = tid & 31;

    const float* __restrict__ in = (SEL == 0) ? (const float*)g_agg : in_ext;

    float f[C_IN];
    #pragma unroll
    for (int c = 0; c < C_IN; c++) f[c] = in[c * N_PTS + n];

    float* outp = (SEL == 0) ? g_ypre : g_rpre;

    #pragma unroll 2
    for (int o = 0; o < C_OUT; o++) {
        float acc = bs[o];
        #pragma unroll
        for (int c4 = 0; c4 < C_IN/4; c4++) {
            float4 w4 = Ws[o * (C_IN/4) + c4];
            acc = fmaf(f[c4*4+0], w4.x, acc);
            acc = fmaf(f[c4*4+1], w4.y, acc);
            acc = fmaf(f[c4*4+2], w4.z, acc);
            acc = fmaf(f[c4*4+3], w4.w, acc);
        }
        outp[o * N_PTS + n] = acc;

        float s1 = acc, s2 = acc * acc;
        #pragma unroll
        for (int off = 16; off; off >>= 1) {
            s1 += __shfl_xor_sync(0xffffffffu, s1, off);
            s2 += __shfl_xor_sync(0xffffffffu, s2, off);
        }
        if (lane == 0) { atomicAdd(&ssum[o], s1); atomicAdd(&ssq[o], s2); }
    }
    __syncthreads();

    int sbase = (SEL == 0) ? 0 : 2 * C_OUT;
    for (int i = tid; i < C_OUT; i += 256) {
        atomicAdd(&g_stats[sbase + i], ssum[i]);
        atomicAdd(&g_stats[sbase + C_OUT + i], ssq[i]);
    }
}

// ---------------------------------------------------------------------------
// Finalize: BN + ReLU on both paths, add, write output [128][N].
__global__ __launch_bounds__(256) void k_final(
    const float* __restrict__ gf, const float* __restrict__ btf,
    const float* __restrict__ gr, const float* __restrict__ btr,
    float* __restrict__ out)
{
    int i = blockIdx.x * 256 + threadIdx.x;   // over 128*32768
    int o = i >> 15;                           // channel
    const float inv = 1.0f / (float)N_PTS;

    float mf = g_stats[o] * inv;
    float vf = g_stats[C_OUT + o] * inv - mf * mf;
    float rf = rsqrtf(vf + EPSBN);

    float mr = g_stats[2*C_OUT + o] * inv;
    float vr = g_stats[3*C_OUT + o] * inv - mr * mr;
    float rr = rsqrtf(vr + EPSBN);

    float y = fmaxf((g_ypre[i] - mf) * rf * gf[o] + btf[o], 0.0f);
    float r = fmaxf((g_rpre[i] - mr) * rr * gr[o] + btr[o], 0.0f);
    out[i] = y + r;
}

// ---------------------------------------------------------------------------
extern "C" void kernel_launch(void* const* d_in, const int* in_sizes, int n_in,
                              void* d_out, int out_size) {
    const float* xyz   = (const float*)d_in[0];   // (1, N, 3)
    const float* pf    = (const float*)d_in[1];   // (1, 64, N)
    const float* np    = (const float*)d_in[2];   // (1, 67, N, 32)
    const float* Wint  = (const float*)d_in[3];
    const float* bint  = (const float*)d_in[4];
    const float* Wfeat = (const float*)d_in[5];
    const float* bfeat = (const float*)d_in[6];
    const float* gfeat = (const float*)d_in[7];
    const float* befeat= (const float*)d_in[8];
    const float* Wres  = (const float*)d_in[9];
    const float* bres  = (const float*)d_in[10];
    const float* gres  = (const float*)d_in[11];
    const float* beres = (const float*)d_in[12];
    float* out = (float*)d_out;

    k_zero_stats<<<1, 4 * C_OUT>>>();
    k_agg<<<N_PTS / 32, 1024>>>(xyz, np, Wint, bint);
    k_gemv_stats<1><<<N_PTS / 256, 256>>>(pf, Wres, bres);        // residual path
    k_gemv_stats<0><<<N_PTS / 256, 256>>>(nullptr, Wfeat, bfeat); // feature path (reads g_agg)
    k_final<<<(C_OUT * N_PTS) / 256, 256>>>(gfeat, befeat, gres, beres, out);
}

// round 2
// speedup vs baseline: 1.1681x; 1.1681x over previous
#include <cuda_runtime.h>
#include <cuda_bf16.h>

#define N_PTS   32768
#define S_NBR   32
#define C_IN    64
#define C_OUT   128
#define NS      (N_PTS * S_NBR)   // 1048576
#define EPSBN   1e-5f

// Scratch (device globals; no allocation allowed)
__device__ float g_ypre[C_OUT * N_PTS];   // [o][n] 16 MB  (feature pre-BN)
__device__ float g_rpre[C_OUT * N_PTS];   // [o][n] 16 MB  (residual pre-BN)
__device__ float g_cA[2 * C_OUT];         // BN scale  [feat | res]
__device__ float g_cB[2 * C_OUT];         // BN shift  [feat | res]

// ---------------------------------------------------------------------------
// Fused aggregation + feature GEMV.
// Block: 256 threads, 32 points.
// Phase 1: warp handles 4 points (lane = neighbour s), shfl-reduce over s,
//          result aggs[c][point-in-block].
// Phase 2: lane = point, warp = 16-output-channel slab. 16 independent FMA
//          chains per thread, W broadcast from smem, coalesced stores.
__global__ __launch_bounds__(256) void k_agg_fused(
    const float* __restrict__ xyz,     // [N][3]
    const float* __restrict__ np,      // [67][N][S]
    const float* __restrict__ Wint,    // [64][3]
    const float* __restrict__ bint,    // [64]
    const float* __restrict__ Wfeat,   // [128][64]
    const float* __restrict__ bfeat)   // [128]
{
    __shared__ float4 wq[C_IN];              // {w0,w1,w2,bias}
    __shared__ float  aggs[C_IN][32];        // [c][point-in-block]
    __shared__ float4 Ws[C_OUT * (C_IN/4)];  // 32 KB, row-major [o][c4]
    __shared__ float  bs[C_OUT];

    int tid  = threadIdx.x;
    int warp = tid >> 5;
    int lane = tid & 31;
    int n0   = blockIdx.x * 32;

    if (tid < C_IN)
        wq[tid] = make_float4(Wint[tid*3+0], Wint[tid*3+1], Wint[tid*3+2], bint[tid]);
    {
        const float4* W4 = (const float4*)Wfeat;
        #pragma unroll
        for (int i = tid; i < C_OUT * (C_IN/4); i += 256) Ws[i] = W4[i];
        if (tid < C_OUT) bs[tid] = bfeat[tid];
    }
    __syncthreads();

    // ---- Phase 1: aggregation ----
    #pragma unroll
    for (int q = 0; q < 4; q++) {
        int w = (warp << 2) | q;          // point within block
        int n = n0 + w;

        float x0 = xyz[n*3 + 0];
        float x1 = xyz[n*3 + 1];
        float x2 = xyz[n*3 + 2];

        int base = (n << 5) | lane;       // n*S + s
        float p0 = np[0*NS + base] - x0;
        float p1 = np[1*NS + base] - x1;
        float p2 = np[2*NS + base] - x2;

        const float* __restrict__ feat = np + 3*NS + base;

        #pragma unroll 8
        for (int c = 0; c < C_IN; c++) {
            float4 wc = wq[c];
            float h = fmaf(p0, wc.x, fmaf(p1, wc.y, fmaf(p2, wc.z, wc.w)));
            h = fmaxf(h, 0.0f);
            float v = h * feat[c * NS];
            v += __shfl_xor_sync(0xffffffffu, v, 16);
            v += __shfl_xor_sync(0xffffffffu, v, 8);
            v += __shfl_xor_sync(0xffffffffu, v, 4);
            v += __shfl_xor_sync(0xffffffffu, v, 2);
            v += __shfl_xor_sync(0xffffffffu, v, 1);
            if (lane == 0) aggs[c][w] = v;
        }
    }
    __syncthreads();

    // ---- Phase 2: GEMV 64 -> 128, thread = (16 outputs, 1 point) ----
    int o0 = warp * 16;
    float acc[16];
    #pragma unroll
    for (int oi = 0; oi < 16; oi++) acc[oi] = bs[o0 + oi];

    #pragma unroll 4
    for (int c4 = 0; c4 < C_IN/4; c4++) {
        float f0 = aggs[c4*4+0][lane];
        float f1 = aggs[c4*4+1][lane];
        float f2 = aggs[c4*4+2][lane];
        float f3 = aggs[c4*4+3][lane];
        #pragma unroll
        for (int oi = 0; oi < 16; oi++) {
            float4 w4 = Ws[(o0 + oi) * (C_IN/4) + c4];
            acc[oi] = fmaf(f0, w4.x, acc[oi]);
            acc[oi] = fmaf(f1, w4.y, acc[oi]);
            acc[oi] = fmaf(f2, w4.z, acc[oi]);
            acc[oi] = fmaf(f3, w4.w, acc[oi]);
        }
    }

    int n = n0 + lane;
    #pragma unroll
    for (int oi = 0; oi < 16; oi++)
        g_ypre[(o0 + oi) * N_PTS + n] = acc[oi];   // coalesced 128B per o-row
}

// ---------------------------------------------------------------------------
// Residual GEMV 64 -> 128 (input from global [64][N]), same tiling.
__global__ __launch_bounds__(256) void k_gemv_res(
    const float* __restrict__ in,      // [64][N]
    const float* __restrict__ W,       // [128][64]
    const float* __restrict__ b)       // [128]
{
    __shared__ float  ftile[C_IN][32];
    __shared__ float4 Ws[C_OUT * (C_IN/4)];
    __shared__ float  bs[C_OUT];

    int tid  = threadIdx.x;
    int warp = tid >> 5;
    int lane = tid & 31;
    int n0   = blockIdx.x * 32;

    {
        const float4* W4 = (const float4*)W;
        #pragma unroll
        for (int i = tid; i < C_OUT * (C_IN/4); i += 256) Ws[i] = W4[i];
        if (tid < C_OUT) bs[tid] = b[tid];
    }
    #pragma unroll
    for (int i = tid; i < C_IN * 32; i += 256) {
        int c = i >> 5, col = i & 31;
        ftile[c][col] = in[c * N_PTS + n0 + col];   // coalesced
    }
    __syncthreads();

    int o0 = warp * 16;
    float acc[16];
    #pragma unroll
    for (int oi = 0; oi < 16; oi++) acc[oi] = bs[o0 + oi];

    #pragma unroll 4
    for (int c4 = 0; c4 < C_IN/4; c4++) {
        float f0 = ftile[c4*4+0][lane];
        float f1 = ftile[c4*4+1][lane];
        float f2 = ftile[c4*4+2][lane];
        float f3 = ftile[c4*4+3][lane];
        #pragma unroll
        for (int oi = 0; oi < 16; oi++) {
            float4 w4 = Ws[(o0 + oi) * (C_IN/4) + c4];
            acc[oi] = fmaf(f0, w4.x, acc[oi]);
            acc[oi] = fmaf(f1, w4.y, acc[oi]);
            acc[oi] = fmaf(f2, w4.z, acc[oi]);
            acc[oi] = fmaf(f3, w4.w, acc[oi]);
        }
    }

    int n = n0 + lane;
    #pragma unroll
    for (int oi = 0; oi < 16; oi++)
        g_rpre[(o0 + oi) * N_PTS + n] = acc[oi];
}

// ---------------------------------------------------------------------------
// BN stats: one block per (channel, path). No atomics. Emits scale/shift.
__global__ __launch_bounds__(256) void k_stats(
    const float* __restrict__ gf, const float* __restrict__ btf,
    const float* __restrict__ gr, const float* __restrict__ btr)
{
    __shared__ float ws1[8], ws2[8];

    int o   = blockIdx.x & (C_OUT - 1);
    int buf = blockIdx.x >> 7;
    int tid = threadIdx.x;

    const float4* src = (const float4*)((buf ? g_rpre : g_ypre) + o * N_PTS);

    float s1 = 0.0f, s2 = 0.0f;
    #pragma unroll 4
    for (int i = tid; i < N_PTS/4; i += 256) {
        float4 v = src[i];
        s1 += v.x + v.y + v.z + v.w;
        s2 += v.x*v.x + v.y*v.y + v.z*v.z + v.w*v.w;
    }
    #pragma unroll
    for (int off = 16; off; off >>= 1) {
        s1 += __shfl_xor_sync(0xffffffffu, s1, off);
        s2 += __shfl_xor_sync(0xffffffffu, s2, off);
    }
    int warp = tid >> 5, lane = tid & 31;
    if (lane == 0) { ws1[warp] = s1; ws2[warp] = s2; }
    __syncthreads();
    if (tid == 0) {
        float t1 = 0.0f, t2 = 0.0f;
        #pragma unroll
        for (int w = 0; w < 8; w++) { t1 += ws1[w]; t2 += ws2[w]; }
        const float inv = 1.0f / (float)N_PTS;
        float mean = t1 * inv;
        float var  = t2 * inv - mean * mean;
        float gamma = buf ? gr[o] : gf[o];
        float beta  = buf ? btr[o] : btf[o];
        float A = gamma * rsqrtf(var + EPSBN);
        g_cA[buf * C_OUT + o] = A;
        g_cB[buf * C_OUT + o] = beta - mean * A;
    }
}

// ---------------------------------------------------------------------------
// Finalize: BN affine + ReLU on both paths, add, float4 throughout.
__global__ __launch_bounds__(256) void k_final(float* __restrict__ out)
{
    int i4 = blockIdx.x * 256 + threadIdx.x;    // float4 index
    int o  = i4 >> 13;                          // channel (N/4 = 8192 per row)

    float Af = g_cA[o],         Bf = g_cB[o];
    float Ar = g_cA[C_OUT + o], Br = g_cB[C_OUT + o];

    float4 y = ((const float4*)g_ypre)[i4];
    float4 r = ((const float4*)g_rpre)[i4];
    float4 v;
    v.x = fmaxf(fmaf(y.x, Af, Bf), 0.0f) + fmaxf(fmaf(r.x, Ar, Br), 0.0f);
    v.y = fmaxf(fmaf(y.y, Af, Bf), 0.0f) + fmaxf(fmaf(r.y, Ar, Br), 0.0f);
    v.z = fmaxf(fmaf(y.z, Af, Bf), 0.0f) + fmaxf(fmaf(r.z, Ar, Br), 0.0f);
    v.w = fmaxf(fmaf(y.w, Af, Bf), 0.0f) + fmaxf(fmaf(r.w, Ar, Br), 0.0f);
    ((float4*)out)[i4] = v;
}

// ---------------------------------------------------------------------------
extern "C" void kernel_launch(void* const* d_in, const int* in_sizes, int n_in,
                              void* d_out, int out_size) {
    const float* xyz   = (const float*)d_in[0];   // (1, N, 3)
    const float* pf    = (const float*)d_in[1];   // (1, 64, N)
    const float* np    = (const float*)d_in[2];   // (1, 67, N, 32)
    const float* Wint  = (const float*)d_in[3];
    const float* bint  = (const float*)d_in[4];
    const float* Wfeat = (const float*)d_in[5];
    const float* bfeat = (const float*)d_in[6];
    const float* gfeat = (const float*)d_in[7];
    const float* befeat= (const float*)d_in[8];
    const float* Wres  = (const float*)d_in[9];
    const float* bres  = (const float*)d_in[10];
    const float* gres  = (const float*)d_in[11];
    const float* beres = (const float*)d_in[12];
    float* out = (float*)d_out;

    k_agg_fused<<<N_PTS / 32, 256>>>(xyz, np, Wint, bint, Wfeat, bfeat);
    k_gemv_res<<<N_PTS / 32, 256>>>(pf, Wres, bres);
    k_stats<<<2 * C_OUT, 256>>>(gfeat, befeat, gres, beres);
    k_final<<<(C_OUT * N_PTS / 4) / 256, 256>>>(out);
}